// round 6
// baseline (speedup 1.0000x reference)
#include <cuda_runtime.h>
#include <math.h>

constexpr int D    = 128;
constexpr int NR   = 20;
constexpr int ET   = 128;   // edges per CTA
constexpr int NT   = 256;   // threads per CTA
constexpr int EMAX = 200000;
constexpr int NBMAX = 16384;

// ---- device scratch (no allocations allowed) ----
__device__ float g_acc;                 // sum of r^2 (global Frobenius norm^2)
__device__ float g_W1T[D * D];          // W1T[k][f]
__device__ float g_W2T[D * 3 * D];      // W2T[k][ch]
__device__ float g_WwT[NR * 3 * D];     // WwT[n][ch]
__device__ int   g_hist[NBMAX + 1];
__device__ int   g_off[NBMAX + 1];
__device__ int   g_cur[NBMAX + 1];
__device__ int   g_pos[EMAX];
__device__ float g_s0[(size_t)EMAX * D];   // slot-ordered s0 (102 MB)
__device__ float g_s1[(size_t)EMAX * D];   // slot-ordered s1 (102 MB)
__device__ float g_s2[(size_t)EMAX * D];   // slot-ordered s2 (102 MB)
__device__ float4 g_meta[EMAX];            // per-slot: org.xyz, edge-id (as int bits)

// ---- smem layout (floats) ----
constexpr int OFF_A   = 0;                    // 128 x 132 (padded activations / h)
constexpr int OFF_W   = OFF_A  + ET * 132;    // 128 x 128 (current weight tile, [k][f])
constexpr int OFF_WW  = OFF_W  + D * D;       // 20 x 384
constexpr int OFF_FC  = OFF_WW + NR * 3 * D;  // 128 x 20
constexpr int OFF_B1  = OFF_FC + ET * NR;     // 128
constexpr int OFF_B2  = OFF_B1 + D;           // 384
constexpr int OFF_BW  = OFF_B2 + 3 * D;       // 384
constexpr int OFF_POS = OFF_BW + 3 * D;       // 128 ints
constexpr int SMEM_FLOATS = OFF_POS + ET;
constexpr size_t SMEM_BYTES = (size_t)SMEM_FLOATS * 4;   // ~175 KB

// ---- packed f32x2 helpers (Blackwell) ----
__device__ __forceinline__ void ffma2(unsigned long long& d, unsigned long long a, unsigned long long b) {
    asm("fma.rn.f32x2 %0, %1, %2, %0;" : "+l"(d) : "l"(a), "l"(b));
}
__device__ __forceinline__ unsigned long long dup2(float x) {
    unsigned long long r; asm("mov.b64 %0, {%1, %1};" : "=l"(r) : "f"(x)); return r;
}
__device__ __forceinline__ unsigned long long pack2(float x, float y) {
    unsigned long long r; asm("mov.b64 %0, {%1, %2};" : "=l"(r) : "f"(x), "f"(y)); return r;
}
__device__ __forceinline__ float2 unpack2(unsigned long long v) {
    float2 f; asm("mov.b64 {%0, %1}, %2;" : "=f"(f.x), "=f"(f.y) : "l"(v)); return f;
}

// ============================================================
__global__ void init_kernel(int N) {
    int i = blockIdx.x * blockDim.x + threadIdx.x;
    if (i <= N) g_hist[i] = 0;
    if (i == 0) g_acc = 0.f;
}

__global__ void norm_kernel(const float* __restrict__ r, int n) {
    __shared__ float red[NT];
    float s = 0.f;
    for (int i = blockIdx.x * blockDim.x + threadIdx.x; i < n; i += gridDim.x * blockDim.x) {
        float x = r[i];
        s += x * x;
    }
    red[threadIdx.x] = s;
    __syncthreads();
    for (int off = NT / 2; off > 0; off >>= 1) {
        if (threadIdx.x < off) red[threadIdx.x] += red[threadIdx.x + off];
        __syncthreads();
    }
    if (threadIdx.x == 0) atomicAdd(&g_acc, red[0]);
}

__global__ void hist_kernel(const int* __restrict__ idx_i, int E) {
    int e = blockIdx.x * blockDim.x + threadIdx.x;
    if (e < E) atomicAdd(&g_hist[idx_i[e]], 1);
}

// single-CTA exclusive scan of g_hist[0..N) -> g_off / g_cur; g_off[N] = E
__global__ void scan_kernel(int N, int E) {
    __shared__ int sh[1024];
    int t = threadIdx.x;
    int CH = (N + 1023) >> 10;
    int b = t * CH, e = min(b + CH, N);
    int s = 0;
    for (int i = b; i < e; i++) s += g_hist[i];
    sh[t] = s;
    __syncthreads();
    for (int off = 1; off < 1024; off <<= 1) {
        int add = (t >= off) ? sh[t - off] : 0;
        __syncthreads();
        sh[t] += add;
        __syncthreads();
    }
    int excl = sh[t] - s;
    for (int i = b; i < e; i++) {
        g_off[i] = excl;
        g_cur[i] = excl;
        excl += g_hist[i];
    }
    if (t == 0) g_off[N] = E;
}

__global__ void pos_kernel(const int* __restrict__ idx_i, int E) {
    int e = blockIdx.x * blockDim.x + threadIdx.x;
    if (e < E) g_pos[e] = atomicAdd(&g_cur[idx_i[e]], 1);
}

// generic transpose: src is R x C row-major; dst[c*R + r] = src[r*C + c]
__global__ void transpose_kernel(const float* __restrict__ src, int R, int C, int which) {
    __shared__ float tile[32][33];
    float* dst = (which == 0) ? g_W1T : (which == 1) ? g_W2T : g_WwT;
    int c0 = blockIdx.x * 32, r0 = blockIdx.y * 32;
    for (int j = threadIdx.y; j < 32; j += 8) {
        int y = r0 + j, x = c0 + threadIdx.x;
        if (y < R && x < C) tile[j][threadIdx.x] = src[y * C + x];
    }
    __syncthreads();
    for (int j = threadIdx.y; j < 32; j += 8) {
        int yc = c0 + j, xr = r0 + threadIdx.x;
        if (yc < C && xr < R) dst[yc * R + xr] = tile[threadIdx.x][j];
    }
}

// ============================================================
// 8x8 GEMM tile with packed f32x2 FMAs.
__device__ __forceinline__ void gemm8x8(const float* __restrict__ sArow,
                                        const float* __restrict__ sW,
                                        int tx, unsigned long long acc[8][4]) {
#pragma unroll 4
    for (int k = 0; k < D; k += 2) {
        unsigned long long b0[4], b1[4];
#pragma unroll
        for (int j = 0; j < 4; j++) {
            b0[j] = *(const unsigned long long*)(sW + k * D + j * 32 + tx * 2);
            b1[j] = *(const unsigned long long*)(sW + (k + 1) * D + j * 32 + tx * 2);
        }
#pragma unroll
        for (int i = 0; i < 8; i++) {
            float2 a = *(const float2*)(sArow + i * 132 + k);
            unsigned long long a0 = dup2(a.x), a1 = dup2(a.y);
#pragma unroll
            for (int j = 0; j < 4; j++) ffma2(acc[i][j], a0, b0[j]);
#pragma unroll
            for (int j = 0; j < 4; j++) ffma2(acc[i][j], a1, b1[j]);
        }
    }
}

__device__ __forceinline__ void zero_acc(unsigned long long acc[8][4]) {
#pragma unroll
    for (int i = 0; i < 8; i++)
#pragma unroll
        for (int j = 0; j < 4; j++) acc[i][j] = 0ull;
}

__device__ __forceinline__ void stage_w2(float* __restrict__ sW, int c, int tid) {
    const float4* src = reinterpret_cast<const float4*>(g_W2T);
    float4* dst = reinterpret_cast<float4*>(sW);
    for (int i = tid; i < D * 32; i += NT) {
        int k = i >> 5, fq = i & 31;
        dst[i] = src[k * 96 + c * 32 + fq];
    }
}

// gate for two edges: wv = bw + fcut(e,:) @ WwT (one chunk's 8 features, packed)
__device__ __forceinline__ void gate_pair(const float* __restrict__ sm, int eA, int eB, int chb,
                                          unsigned long long wvA[4], unsigned long long wvB[4]) {
#pragma unroll
    for (int j = 0; j < 4; j++) {
        unsigned long long bwp = *(const unsigned long long*)(sm + OFF_BW + chb + j * 32);
        wvA[j] = bwp; wvB[j] = bwp;
    }
    const float* fA = sm + OFF_FC + eA * NR;
    const float* fB = sm + OFF_FC + eB * NR;
#pragma unroll
    for (int n = 0; n < NR; n++) {
        unsigned long long a = dup2(fA[n]), b = dup2(fB[n]);
        const float* wwr = sm + OFF_WW + n * 3 * D + chb;
#pragma unroll
        for (int j = 0; j < 4; j++) {
            unsigned long long w2 = *(const unsigned long long*)(wwr + j * 32);
            ffma2(wvA[j], a, w2);
            ffma2(wvB[j], b, w2);
        }
    }
}

// store one chunk's gated result to a slot-ordered scratch array
__device__ __forceinline__ void store_chunk(
    float* __restrict__ dst_base, const float* __restrict__ sm,
    const int* __restrict__ sPos, unsigned long long acc[8][4],
    int chunk, int e0, int er0, int tx, int E)
{
    const int chb = chunk * D + tx * 2;
    float2 b2p[4];
#pragma unroll
    for (int j = 0; j < 4; j++) b2p[j] = *(const float2*)(sm + OFF_B2 + chb + j * 32);
#pragma unroll
    for (int ii = 0; ii < 8; ii += 2) {
        unsigned long long wvA[4], wvB[4];
        gate_pair(sm, er0 + ii, er0 + ii + 1, chb, wvA, wvB);
#pragma unroll
        for (int p = 0; p < 2; p++) {
            int i = ii + p;
            int e = er0 + i;
            if (e0 + e >= E) continue;
            int slot = sPos[e];
            float* dst = dst_base + (size_t)slot * D + tx * 2;
#pragma unroll
            for (int j = 0; j < 4; j++) {
                float2 pa = unpack2(acc[i][j]);
                float2 wa = unpack2(p == 0 ? wvA[j] : wvB[j]);
                *(unsigned long long*)(dst + j * 32) =
                    pack2(wa.x * (pa.x + b2p[j].x), wa.y * (pa.y + b2p[j].y));
            }
        }
    }
}

// ============================================================
__global__ void __launch_bounds__(NT, 1) fused_kernel(
    const float* __restrict__ s, const float* __restrict__ r,
    const float* __restrict__ b1, const float* __restrict__ b2, const float* __restrict__ bw,
    int E)
{
    extern __shared__ float sm[];
    float* sA  = sm + OFF_A;
    float* sW  = sm + OFF_W;
    int*   sPos = reinterpret_cast<int*>(sm + OFF_POS);

    const int tid = threadIdx.x;
    const int e0  = blockIdx.x * ET;
    const int tx  = tid & 15;        // feature pair base tx*2, groups j*32
    const int ty  = tid >> 4;        // edges ty*8 .. ty*8+7
    const int er0 = ty * 8;

    // ---- stage s tile (rows padded to 132 floats) ----
    {
        const float4* src = reinterpret_cast<const float4*>(s) + (size_t)e0 * 32;
        for (int i = tid; i < ET * 32; i += NT) {
            int e = i >> 5, dq = i & 31;
            float4 val = (e0 + e < E) ? src[i] : make_float4(0.f, 0.f, 0.f, 0.f);
            *reinterpret_cast<float4*>(sA + e * 132 + dq * 4) = val;
        }
    }
    // ---- stage W1T ----
    {
        const float4* src = reinterpret_cast<const float4*>(g_W1T);
        float4* dst = reinterpret_cast<float4*>(sW);
        for (int i = tid; i < D * 32; i += NT) dst[i] = src[i];
    }
    // ---- stage WwT ----
    {
        const float4* src = reinterpret_cast<const float4*>(g_WwT);
        float4* dst = reinterpret_cast<float4*>(sm + OFF_WW);
        for (int i = tid; i < NR * 96; i += NT) dst[i] = src[i];
    }
    // ---- biases ----
    for (int i = tid; i < D; i += NT) sm[OFF_B1 + i] = b1[i];
    for (int i = tid; i < 3 * D; i += NT) { sm[OFF_B2 + i] = b2[i]; sm[OFF_BW + i] = bw[i]; }
    // ---- per-edge: slot, meta(org+eid), fcut via sin recurrence ----
    if (tid < ET) {
        int ge = e0 + tid;
        if (ge < E) {
            int slot = g_pos[ge];
            sPos[tid] = slot;
            float rx = r[ge * 3 + 0], ry = r[ge * 3 + 1], rz = r[ge * 3 + 2];
            float rn = sqrtf(rx * rx + ry * ry + rz * rz);
            float invg = rsqrtf(g_acc);   // reference: r / ||r||_F (whole array!)
            float4 meta;
            meta.x = rx * invg; meta.y = ry * invg; meta.z = rz * invg;
            meta.w = __int_as_float(ge);
            g_meta[slot] = meta;
            float inv_rn = 1.f / rn;
            float theta = 0.62831853071795864f * rn;   // pi/RCUT * rn
            float sb = sinf(theta), cb = cosf(theta);
            float twocb = 2.f * cb;
            float sm1 = 0.f, scur = sb;
#pragma unroll
            for (int n = 0; n < NR; n++) {
                float rbf = scur * inv_rn;
                float fc = (rbf <= 5.0f) ? 0.5f * (__cosf(0.62831853071795864f * rbf) + 1.0f) : 0.0f;
                sm[OFF_FC + tid * NR + n] = fc;
                float nxt = twocb * scur - sm1;
                sm1 = scur; scur = nxt;
            }
        } else {
            sPos[tid] = 0;
#pragma unroll
            for (int n = 0; n < NR; n++) sm[OFF_FC + tid * NR + n] = 0.f;
        }
    }
    __syncthreads();

    unsigned long long acc[8][4];

    // ================= GEMM1: h = silu(S @ W1^T + b1) =================
    zero_acc(acc);
    gemm8x8(sA + er0 * 132, sW, tx, acc);
    __syncthreads();   // all reads of sA / sW done

    {
        float2 bb[4];
#pragma unroll
        for (int j = 0; j < 4; j++) bb[j] = *(const float2*)(sm + OFF_B1 + tx * 2 + j * 32);
#pragma unroll
        for (int i = 0; i < 8; i++) {
#pragma unroll
            for (int j = 0; j < 4; j++) {
                float2 p = unpack2(acc[i][j]);
                float x0 = p.x + bb[j].x, x1 = p.y + bb[j].y;
                float h0 = x0 / (1.f + __expf(-x0));
                float h1 = x1 / (1.f + __expf(-x1));
                *(unsigned long long*)(sA + (er0 + i) * 132 + tx * 2 + j * 32) = pack2(h0, h1);
            }
        }
    }
    stage_w2(sW, 0, tid);
    __syncthreads();

    // ================= chunk 0 -> g_s0 =================
    zero_acc(acc);
    gemm8x8(sA + er0 * 132, sW, tx, acc);
    __syncthreads();
    stage_w2(sW, 1, tid);
    store_chunk(g_s0, sm, sPos, acc, 0, e0, er0, tx, E);
    __syncthreads();

    // ================= chunk 1 -> g_s1 =================
    zero_acc(acc);
    gemm8x8(sA + er0 * 132, sW, tx, acc);
    __syncthreads();
    stage_w2(sW, 2, tid);
    store_chunk(g_s1, sm, sPos, acc, 1, e0, er0, tx, E);
    __syncthreads();

    // ================= chunk 2 -> g_s2 =================
    zero_acc(acc);
    gemm8x8(sA + er0 * 132, sW, tx, acc);
    store_chunk(g_s2, sm, sPos, acc, 2, e0, er0, tx, E);
}

// ============================================================
// one CTA (128 threads) per node: sum contiguous slot range, write outputs.
// vv = s2*org + s0*v[eid]; out_s = sum s1. No atomics anywhere.
__global__ void __launch_bounds__(128) gather_kernel(
    const float* __restrict__ v, float* __restrict__ out_v, float* __restrict__ out_s)
{
    int n = blockIdx.x;
    int beg = g_off[n], end = g_off[n + 1];
    int t = threadIdx.x;     // feature: t owns f = t (0..127)

    float av0 = 0.f, av1 = 0.f, av2 = 0.f, as1 = 0.f;
    for (int slot = beg; slot < end; slot++) {
        float4 meta = g_meta[slot];
        int eid = __float_as_int(meta.w);
        float s0 = g_s0[(size_t)slot * D + t];
        float s1 = g_s1[(size_t)slot * D + t];
        float s2 = g_s2[(size_t)slot * D + t];
        const float* vrow = v + (size_t)eid * 3 * D + t;
        av0 += s2 * meta.x + s0 * vrow[0];
        av1 += s2 * meta.y + s0 * vrow[D];
        av2 += s2 * meta.z + s0 * vrow[2 * D];
        as1 += s1;
    }
    float* ov = out_v + (size_t)n * 3 * D + t;
    ov[0]     = av0;
    ov[D]     = av1;
    ov[2 * D] = av2;
    out_s[(size_t)n * D + t] = as1;
}

// ============================================================
extern "C" void kernel_launch(void* const* d_in, const int* in_sizes, int n_in,
                              void* d_out, int out_size) {
    const float* s   = (const float*)d_in[0];
    const float* r   = (const float*)d_in[1];
    const float* v   = (const float*)d_in[2];
    const float* W1  = (const float*)d_in[3];
    const float* b1  = (const float*)d_in[4];
    const float* W2  = (const float*)d_in[5];
    const float* b2  = (const float*)d_in[6];
    const float* Ww  = (const float*)d_in[7];
    const float* bw  = (const float*)d_in[8];
    const int*   idx = (const int*)d_in[9];
    const int E = in_sizes[9];
    const int N = out_size / (4 * D);            // out = N*3*D (out_v) + N*D (out_s)
    float* out_v = (float*)d_out;
    float* out_s = out_v + (size_t)N * 3 * D;

    cudaFuncSetAttribute(fused_kernel, cudaFuncAttributeMaxDynamicSharedMemorySize, (int)SMEM_BYTES);

    // CSR build: hist -> scan -> pos
    init_kernel<<<(N + NT) / NT, NT>>>(N);
    norm_kernel<<<256, NT>>>(r, E * 3);
    hist_kernel<<<(E + NT - 1) / NT, NT>>>(idx, E);
    scan_kernel<<<1, 1024>>>(N, E);
    pos_kernel<<<(E + NT - 1) / NT, NT>>>(idx, E);

    dim3 tb(32, 8);
    transpose_kernel<<<dim3(4, 4),  tb>>>(W1, D, D, 0);          // -> g_W1T [k][f]
    transpose_kernel<<<dim3(4, 12), tb>>>(W2, 3 * D, D, 1);      // -> g_W2T [k][ch]
    transpose_kernel<<<dim3(1, 12), tb>>>(Ww, 3 * D, NR, 2);     // -> g_WwT [n][ch]

    int grid = (E + ET - 1) / ET;
    fused_kernel<<<grid, NT, SMEM_BYTES>>>(s, r, b1, b2, bw, E);

    gather_kernel<<<N, 128>>>(v, out_v, out_s);
}

// round 7
// speedup vs baseline: 1.6107x; 1.6107x over previous
#include <cuda_runtime.h>
#include <math.h>

constexpr int D    = 128;
constexpr int NR   = 20;
constexpr int ET   = 128;   // edges per CTA
constexpr int NT   = 256;   // threads per CTA (8 warps x 16 rows)
constexpr int EMAX = 200000;
constexpr int NBMAX = 16384;

// ---- device scratch (no allocations allowed) ----
__device__ float g_acc;
__device__ int   g_hist[NBMAX + 1];
__device__ int   g_off[NBMAX + 1];
__device__ int   g_cur[NBMAX + 1];
__device__ int   g_pos[EMAX];
__device__ float g_s0[(size_t)EMAX * D];   // slot-ordered s0
__device__ float g_s1[(size_t)EMAX * D];   // slot-ordered s1
__device__ float g_s2[(size_t)EMAX * D];   // slot-ordered s2
__device__ float4 g_meta[EMAX];            // per-slot: org.xyz, edge-id

// ---- smem layout (32-bit words) ----
constexpr int SA   = 0;                 // 128 x 132  tf32 bits: s, then h (in place)
constexpr int SW   = SA  + 128 * 132;   // 128 x 132  tf32 bits: W1, then W2 chunk c
constexpr int SWW  = SW  + 128 * 132;   // 384 x 28   tf32 bits: Ww (cols 20..27 zero)
constexpr int SFC  = SWW + 384 * 28;    // 128 x 28   tf32 bits: fcut (cols 20..27 zero)
constexpr int SB1  = SFC + 128 * 28;    // 128  f32
constexpr int SB2  = SB1 + 128;         // 384  f32
constexpr int SBW  = SB2 + 384;         // 384  f32
constexpr int SPOS = SBW + 384;         // 128  int
constexpr int SMEMN = SPOS + 128;       // 49152 words = 192 KB
constexpr size_t SMEM_BYTES = (size_t)SMEMN * 4;

// ---- tf32 helpers ----
__device__ __forceinline__ unsigned f2tf(float x) {
    unsigned r; asm("cvt.rna.tf32.f32 %0, %1;" : "=r"(r) : "f"(x)); return r;
}
__device__ __forceinline__ void mma_tf32(float d[4],
    unsigned a0, unsigned a1, unsigned a2, unsigned a3, unsigned b0, unsigned b1) {
    asm("mma.sync.aligned.m16n8k8.row.col.f32.tf32.tf32.f32 "
        "{%0,%1,%2,%3}, {%4,%5,%6,%7}, {%8,%9}, {%0,%1,%2,%3};"
        : "+f"(d[0]), "+f"(d[1]), "+f"(d[2]), "+f"(d[3])
        : "r"(a0), "r"(a1), "r"(a2), "r"(a3), "r"(b0), "r"(b1));
}

// ============================================================ prologue
__global__ void init_kernel(int N) {
    int i = blockIdx.x * blockDim.x + threadIdx.x;
    if (i <= N) g_hist[i] = 0;
    if (i == 0) g_acc = 0.f;
}

__global__ void norm_kernel(const float* __restrict__ r, int n) {
    __shared__ float red[NT];
    float s = 0.f;
    for (int i = blockIdx.x * blockDim.x + threadIdx.x; i < n; i += gridDim.x * blockDim.x) {
        float x = r[i];
        s += x * x;
    }
    red[threadIdx.x] = s;
    __syncthreads();
    for (int off = NT / 2; off > 0; off >>= 1) {
        if (threadIdx.x < off) red[threadIdx.x] += red[threadIdx.x + off];
        __syncthreads();
    }
    if (threadIdx.x == 0) atomicAdd(&g_acc, red[0]);
}

__global__ void hist_kernel(const int* __restrict__ idx_i, int E) {
    int e = blockIdx.x * blockDim.x + threadIdx.x;
    if (e < E) atomicAdd(&g_hist[idx_i[e]], 1);
}

__global__ void scan_kernel(int N, int E) {
    __shared__ int sh[1024];
    int t = threadIdx.x;
    int CH = (N + 1023) >> 10;
    int b = t * CH, e = min(b + CH, N);
    int s = 0;
    for (int i = b; i < e; i++) s += g_hist[i];
    sh[t] = s;
    __syncthreads();
    for (int off = 1; off < 1024; off <<= 1) {
        int add = (t >= off) ? sh[t - off] : 0;
        __syncthreads();
        sh[t] += add;
        __syncthreads();
    }
    int excl = sh[t] - s;
    for (int i = b; i < e; i++) {
        g_off[i] = excl;
        g_cur[i] = excl;
        excl += g_hist[i];
    }
    if (t == 0) g_off[N] = E;
}

__global__ void pos_kernel(const int* __restrict__ idx_i, int E) {
    int e = blockIdx.x * blockDim.x + threadIdx.x;
    if (e < E) g_pos[e] = atomicAdd(&g_cur[idx_i[e]], 1);
}

// ============================================================ fused
__global__ void __launch_bounds__(NT, 1) fused_kernel(
    const float* __restrict__ s, const float* __restrict__ r,
    const float* __restrict__ W1, const float* __restrict__ W2,
    const float* __restrict__ b1, const float* __restrict__ b2,
    const float* __restrict__ Ww, const float* __restrict__ bw, int E)
{
    extern __shared__ unsigned sm[];
    float* smf = reinterpret_cast<float*>(sm);
    int*   sPos = reinterpret_cast<int*>(sm + SPOS);

    const int tid  = threadIdx.x;
    const int lane = tid & 31;
    const int wrp  = tid >> 5;
    const int e0   = blockIdx.x * ET;
    const int rw   = wrp * 16;         // this warp's 16-row band
    const int qr   = lane >> 2;        // 0..7
    const int qc   = lane & 3;         // 0..3

    // ---- stage s -> sA (tf32 bits, stride 132, dead rows zeroed) ----
    for (int i = tid; i < 128 * 32; i += NT) {
        int e = i >> 5, kq = (i & 31) * 4;
        float4 val = (e0 + e < E) ? *(const float4*)(s + (size_t)(e0 + e) * D + kq)
                                  : make_float4(0.f, 0.f, 0.f, 0.f);
        unsigned* dst = sm + SA + e * 132 + kq;
        dst[0] = f2tf(val.x); dst[1] = f2tf(val.y); dst[2] = f2tf(val.z); dst[3] = f2tf(val.w);
    }
    // ---- stage W1 -> sW ----
    for (int i = tid; i < 128 * 32; i += NT) {
        int n = i >> 5, kq = (i & 31) * 4;
        float4 val = *(const float4*)(W1 + (size_t)n * D + kq);
        unsigned* dst = sm + SW + n * 132 + kq;
        dst[0] = f2tf(val.x); dst[1] = f2tf(val.y); dst[2] = f2tf(val.z); dst[3] = f2tf(val.w);
    }
    // ---- stage Ww -> sWW [384][28], cols >= NR zero ----
    for (int i = tid; i < 384 * 7; i += NT) {
        int n = i / 7, q = i - n * 7;
        unsigned* dst = sm + SWW + n * 28 + q * 4;
#pragma unroll
        for (int j = 0; j < 4; j++) {
            int cc = q * 4 + j;
            dst[j] = (cc < NR) ? f2tf(Ww[n * NR + cc]) : 0u;
        }
    }
    // ---- biases ----
    for (int i = tid; i < D; i += NT) smf[SB1 + i] = b1[i];
    for (int i = tid; i < 3 * D; i += NT) { smf[SB2 + i] = b2[i]; smf[SBW + i] = bw[i]; }
    // ---- per-edge: slot, meta(org+eid), fcut (tf32, stride 28) ----
    if (tid < ET) {
        int ge = e0 + tid;
        unsigned* fcrow = sm + SFC + tid * 28;
        if (ge < E) {
            sPos[tid] = g_pos[ge];
            float rx = r[ge * 3 + 0], ry = r[ge * 3 + 1], rz = r[ge * 3 + 2];
            float rn = sqrtf(rx * rx + ry * ry + rz * rz);
            float invg = rsqrtf(g_acc);   // reference: r / ||r||_F (whole array!)
            float4 meta;
            meta.x = rx * invg; meta.y = ry * invg; meta.z = rz * invg;
            meta.w = __int_as_float(ge);
            g_meta[sPos[tid]] = meta;
            float inv_rn = 1.f / rn;
            float theta = 0.62831853071795864f * rn;   // pi/RCUT * rn
            float sb = sinf(theta), cb = cosf(theta);
            float twocb = 2.f * cb;
            float sm1 = 0.f, scur = sb;
#pragma unroll
            for (int n = 0; n < NR; n++) {
                float rbf = scur * inv_rn;
                float fc = (rbf <= 5.0f) ? 0.5f * (__cosf(0.62831853071795864f * rbf) + 1.0f) : 0.0f;
                fcrow[n] = f2tf(fc);
                float nxt = twocb * scur - sm1;
                sm1 = scur; scur = nxt;
            }
            for (int n = NR; n < 28; n++) fcrow[n] = 0u;
        } else {
            sPos[tid] = 0;
            for (int n = 0; n < 28; n++) fcrow[n] = 0u;
        }
    }
    __syncthreads();

    // per-thread constants
    const int rA = rw + qr, rB = rw + qr + 8;
    const bool liveA = (e0 + rA) < E;
    const bool liveB = (e0 + rB) < E;
    const int slotA = sPos[rA];
    const int slotB = sPos[rB];
    const unsigned* pA = sm + SA + rA * 132 + qc;   // a0/a2 base; a1/a3 at +8*132

    // fcut A fragments (3 k-steps of 8), chunk-independent
    unsigned fa[3][4];
#pragma unroll
    for (int t = 0; t < 3; t++) {
        const unsigned* pf = sm + SFC + rA * 28 + t * 8 + qc;
        fa[t][0] = pf[0];
        fa[t][1] = pf[8 * 28];
        fa[t][2] = pf[4];
        fa[t][3] = pf[8 * 28 + 4];
    }

    float acc[16][4];

    // ================= GEMM1: h = silu(S @ W1^T + b1) =================
#pragma unroll
    for (int nt = 0; nt < 16; nt++)
#pragma unroll
        for (int j = 0; j < 4; j++) acc[nt][j] = 0.f;

#pragma unroll 4
    for (int kk = 0; kk < 16; kk++) {
        int k0 = kk * 8;
        unsigned a0 = pA[k0], a1 = pA[8 * 132 + k0], a2 = pA[k0 + 4], a3 = pA[8 * 132 + k0 + 4];
        const unsigned* pB = sm + SW + qr * 132 + k0 + qc;
#pragma unroll
        for (int nt = 0; nt < 16; nt++)
            mma_tf32(acc[nt], a0, a1, a2, a3, pB[nt * 8 * 132], pB[nt * 8 * 132 + 4]);
    }
    __syncthreads();   // all W1 reads + all sA(s) reads complete

    // silu -> h overwrites sA rows (warp-private); stage W2 chunk 0 over W1
    {
        unsigned* hA = sm + SA + rA * 132;
        unsigned* hB = sm + SA + rB * 132;
#pragma unroll
        for (int nt = 0; nt < 16; nt++) {
            int c0 = nt * 8 + 2 * qc;
            float bx = smf[SB1 + c0], by = smf[SB1 + c0 + 1];
            float x0 = acc[nt][0] + bx, x1 = acc[nt][1] + by;
            float x2 = acc[nt][2] + bx, x3 = acc[nt][3] + by;
            hA[c0]     = f2tf(x0 / (1.f + __expf(-x0)));
            hA[c0 + 1] = f2tf(x1 / (1.f + __expf(-x1)));
            hB[c0]     = f2tf(x2 / (1.f + __expf(-x2)));
            hB[c0 + 1] = f2tf(x3 / (1.f + __expf(-x3)));
        }
    }
    for (int i = tid; i < 128 * 32; i += NT) {
        int n = i >> 5, kq = (i & 31) * 4;
        float4 val = *(const float4*)(W2 + (size_t)n * D + kq);
        unsigned* dst = sm + SW + n * 132 + kq;
        dst[0] = f2tf(val.x); dst[1] = f2tf(val.y); dst[2] = f2tf(val.z); dst[3] = f2tf(val.w);
    }
    __syncthreads();

    // ================= chunks 0..2: phi -> gate -> store =================
#pragma unroll 1
    for (int c = 0; c < 3; c++) {
#pragma unroll
        for (int nt = 0; nt < 16; nt++)
#pragma unroll
            for (int j = 0; j < 4; j++) acc[nt][j] = 0.f;

#pragma unroll 4
        for (int kk = 0; kk < 16; kk++) {
            int k0 = kk * 8;
            unsigned a0 = pA[k0], a1 = pA[8 * 132 + k0], a2 = pA[k0 + 4], a3 = pA[8 * 132 + k0 + 4];
            const unsigned* pB = sm + SW + qr * 132 + k0 + qc;
#pragma unroll
            for (int nt = 0; nt < 16; nt++)
                mma_tf32(acc[nt], a0, a1, a2, a3, pB[nt * 8 * 132], pB[nt * 8 * 132 + 4]);
        }
        __syncthreads();   // sW reads done -> safe to restage

        if (c < 2) {       // stage next W2 chunk
            const float* Wsrc = W2 + (size_t)(c + 1) * 128 * D;
            for (int i = tid; i < 128 * 32; i += NT) {
                int n = i >> 5, kq = (i & 31) * 4;
                float4 val = *(const float4*)(Wsrc + (size_t)n * D + kq);
                unsigned* dst = sm + SW + n * 132 + kq;
                dst[0] = f2tf(val.x); dst[1] = f2tf(val.y); dst[2] = f2tf(val.z); dst[3] = f2tf(val.w);
            }
        }

        // gate (3 mma k-steps vs Ww) + bias + multiply + slot-ordered store
        float* gc = (c == 0) ? g_s0 : (c == 1) ? g_s1 : g_s2;
        const unsigned* pWw = sm + SWW + (c * 128 + qr) * 28 + qc;
#pragma unroll
        for (int nt = 0; nt < 16; nt++) {
            float w4[4] = {0.f, 0.f, 0.f, 0.f};
#pragma unroll
            for (int t = 0; t < 3; t++) {
                unsigned b0 = pWw[nt * 8 * 28 + t * 8];
                unsigned b1r = pWw[nt * 8 * 28 + t * 8 + 4];
                mma_tf32(w4, fa[t][0], fa[t][1], fa[t][2], fa[t][3], b0, b1r);
            }
            int f0c = nt * 8 + 2 * qc;
            int ch  = c * 128 + f0c;
            float2 b2p = *(const float2*)(smf + SB2 + ch);
            float2 bwp = *(const float2*)(smf + SBW + ch);
            float o0 = (acc[nt][0] + b2p.x) * (w4[0] + bwp.x);
            float o1 = (acc[nt][1] + b2p.y) * (w4[1] + bwp.y);
            float o2 = (acc[nt][2] + b2p.x) * (w4[2] + bwp.x);
            float o3 = (acc[nt][3] + b2p.y) * (w4[3] + bwp.y);
            if (liveA) *(float2*)(gc + (size_t)slotA * D + f0c) = make_float2(o0, o1);
            if (liveB) *(float2*)(gc + (size_t)slotB * D + f0c) = make_float2(o2, o3);
        }
        __syncthreads();   // restage of sW complete before next chunk's mma
    }
}

// ============================================================ gather
// one CTA (128 threads) per node: sum contiguous slot range, write outputs.
__global__ void __launch_bounds__(128) gather_kernel(
    const float* __restrict__ v, float* __restrict__ out_v, float* __restrict__ out_s)
{
    int n = blockIdx.x;
    int beg = g_off[n], end = g_off[n + 1];
    int t = threadIdx.x;

    float av0 = 0.f, av1 = 0.f, av2 = 0.f, as1 = 0.f;
    for (int slot = beg; slot < end; slot++) {
        float4 meta = g_meta[slot];
        int eid = __float_as_int(meta.w);
        float s0 = g_s0[(size_t)slot * D + t];
        float s1 = g_s1[(size_t)slot * D + t];
        float s2 = g_s2[(size_t)slot * D + t];
        const float* vrow = v + (size_t)eid * 3 * D + t;
        av0 += s2 * meta.x + s0 * vrow[0];
        av1 += s2 * meta.y + s0 * vrow[D];
        av2 += s2 * meta.z + s0 * vrow[2 * D];
        as1 += s1;
    }
    float* ov = out_v + (size_t)n * 3 * D + t;
    ov[0]     = av0;
    ov[D]     = av1;
    ov[2 * D] = av2;
    out_s[(size_t)n * D + t] = as1;
}

// ============================================================
extern "C" void kernel_launch(void* const* d_in, const int* in_sizes, int n_in,
                              void* d_out, int out_size) {
    const float* s   = (const float*)d_in[0];
    const float* r   = (const float*)d_in[1];
    const float* v   = (const float*)d_in[2];
    const float* W1  = (const float*)d_in[3];
    const float* b1  = (const float*)d_in[4];
    const float* W2  = (const float*)d_in[5];
    const float* b2  = (const float*)d_in[6];
    const float* Ww  = (const float*)d_in[7];
    const float* bw  = (const float*)d_in[8];
    const int*   idx = (const int*)d_in[9];
    const int E = in_sizes[9];
    const int N = out_size / (4 * D);
    float* out_v = (float*)d_out;
    float* out_s = out_v + (size_t)N * 3 * D;

    cudaFuncSetAttribute(fused_kernel, cudaFuncAttributeMaxDynamicSharedMemorySize, (int)SMEM_BYTES);

    // 5 prologue launches -> fused is launch #6 (ncu -s 5 lands on it)
    init_kernel<<<(N + NT) / NT, NT>>>(N);
    norm_kernel<<<256, NT>>>(r, E * 3);
    hist_kernel<<<(E + NT - 1) / NT, NT>>>(idx, E);
    scan_kernel<<<1, 1024>>>(N, E);
    pos_kernel<<<(E + NT - 1) / NT, NT>>>(idx, E);

    int grid = (E + ET - 1) / ET;
    fused_kernel<<<grid, NT, SMEM_BYTES>>>(s, r, W1, W2, b1, b2, Ww, bw, E);

    gather_kernel<<<N, 128>>>(v, out_v, out_s);
}

// round 8
// speedup vs baseline: 1.9805x; 1.2296x over previous
#include <cuda_runtime.h>
#include <math.h>

constexpr int D    = 128;
constexpr int NR   = 20;
constexpr int ET   = 128;   // edges per CTA
constexpr int NT   = 512;   // threads per CTA (16 warps = 4M x 4N)
constexpr int EMAX = 200000;
constexpr int NBMAX = 16384;

// ---- device scratch (no allocations allowed) ----
__device__ float g_acc;
__device__ int   g_hist[NBMAX + 1];
__device__ int   g_off[NBMAX + 1];
__device__ int   g_cur[NBMAX + 1];
__device__ int   g_pos[EMAX];
__device__ float g_s0[(size_t)EMAX * D];
__device__ float g_s1[(size_t)EMAX * D];
__device__ float g_s2[(size_t)EMAX * D];
__device__ float4 g_meta[EMAX];            // per-slot: org.xyz, edge-id

// ---- smem layout (32-bit words) ----
// sA / sW use k-interleaved octets: word pos(k) = (k>>3)*8 + (k&3)*2 + ((k>>2)&1),
// row stride 136 (8 mod 32 -> conflict-free LDS.64 fragment loads).
constexpr int SA   = 0;                 // 128 x 136  tf32: s, then h (in place)
constexpr int SW   = SA  + 128 * 136;   // 128 x 136  tf32: W1, then W2 chunk c
constexpr int SWW  = SW  + 128 * 136;   // 384 x 28   tf32: Ww (natural layout, cols>=NR zero)
constexpr int SFC  = SWW + 384 * 28;    // 128 x 28   tf32: fcut (natural layout)
constexpr int SB1  = SFC + 128 * 28;    // 128  f32
constexpr int SB2  = SB1 + 128;         // 384  f32
constexpr int SBW  = SB2 + 384;         // 384  f32
constexpr int SPOS = SBW + 384;         // 128  int
constexpr int SMEMN = SPOS + 128;       // 50176 words = 196 KB
constexpr size_t SMEM_BYTES = (size_t)SMEMN * 4;

// ---- tf32 helpers ----
__device__ __forceinline__ unsigned f2tf(float x) {
    unsigned r; asm("cvt.rna.tf32.f32 %0, %1;" : "=r"(r) : "f"(x)); return r;
}
__device__ __forceinline__ void mma_tf32(float d[4],
    unsigned a0, unsigned a1, unsigned a2, unsigned a3, unsigned b0, unsigned b1) {
    asm("mma.sync.aligned.m16n8k8.row.col.f32.tf32.tf32.f32 "
        "{%0,%1,%2,%3}, {%4,%5,%6,%7}, {%8,%9}, {%0,%1,%2,%3};"
        : "+f"(d[0]), "+f"(d[1]), "+f"(d[2]), "+f"(d[3])
        : "r"(a0), "r"(a1), "r"(a2), "r"(a3), "r"(b0), "r"(b1));
}
__device__ __forceinline__ uint2 lds64(const unsigned* p) {
    uint2 v; asm("ld.shared.v2.b32 {%0,%1}, [%2];" : "=r"(v.x), "=r"(v.y)
                 : "l"((unsigned long long)__cvta_generic_to_shared(p)));
    return v;
}

// ============================================================ prologue
__global__ void init_kernel(int N) {
    int i = blockIdx.x * blockDim.x + threadIdx.x;
    if (i <= N) g_hist[i] = 0;
    if (i == 0) g_acc = 0.f;
}

// histogram + global ||r||^2 in one pass
__global__ void hist_norm_kernel(const int* __restrict__ idx_i, const float* __restrict__ r, int E) {
    __shared__ float red[256];
    int e = blockIdx.x * blockDim.x + threadIdx.x;
    float s = 0.f;
    if (e < E) {
        atomicAdd(&g_hist[idx_i[e]], 1);
        float rx = r[e * 3 + 0], ry = r[e * 3 + 1], rz = r[e * 3 + 2];
        s = rx * rx + ry * ry + rz * rz;
    }
    red[threadIdx.x] = s;
    __syncthreads();
    for (int off = 128; off > 0; off >>= 1) {
        if (threadIdx.x < off) red[threadIdx.x] += red[threadIdx.x + off];
        __syncthreads();
    }
    if (threadIdx.x == 0) atomicAdd(&g_acc, red[0]);
}

__global__ void scan_kernel(int N, int E) {
    __shared__ int sh[1024];
    int t = threadIdx.x;
    int CH = (N + 1023) >> 10;
    int b = t * CH, e = min(b + CH, N);
    int s = 0;
    for (int i = b; i < e; i++) s += g_hist[i];
    sh[t] = s;
    __syncthreads();
    for (int off = 1; off < 1024; off <<= 1) {
        int add = (t >= off) ? sh[t - off] : 0;
        __syncthreads();
        sh[t] += add;
        __syncthreads();
    }
    int excl = sh[t] - s;
    for (int i = b; i < e; i++) {
        g_off[i] = excl;
        g_cur[i] = excl;
        excl += g_hist[i];
    }
    if (t == 0) g_off[N] = E;
}

__global__ void pos_kernel(const int* __restrict__ idx_i, int E) {
    int e = blockIdx.x * blockDim.x + threadIdx.x;
    if (e < E) g_pos[e] = atomicAdd(&g_cur[idx_i[e]], 1);
}

// ============================================================ fused
__global__ void __launch_bounds__(NT, 1) fused_kernel(
    const float* __restrict__ s, const float* __restrict__ r,
    const float* __restrict__ W1, const float* __restrict__ W2,
    const float* __restrict__ b1, const float* __restrict__ b2,
    const float* __restrict__ Ww, const float* __restrict__ bw, int E)
{
    extern __shared__ unsigned sm[];
    float* smf = reinterpret_cast<float*>(sm);
    int*   sPos = reinterpret_cast<int*>(sm + SPOS);

    const int tid  = threadIdx.x;
    const int lane = tid & 31;
    const int wrp  = tid >> 5;
    const int e0   = blockIdx.x * ET;
    const int mw   = wrp >> 2;         // 0..3 -> rows m0..m0+31
    const int nw   = wrp & 3;          // 0..3 -> cols n0..n0+31
    const int m0   = mw * 32;
    const int n0   = nw * 32;
    const int qr   = lane >> 2;        // 0..7
    const int qc   = lane & 3;         // 0..3

    // ---- stage s -> sA (tf32, k-interleaved, stride 136) ----
    for (int i = tid; i < 128 * 32; i += NT) {
        int e = i >> 5, q = i & 31;          // k quad q: k = 4q..4q+3
        float4 val = (e0 + e < E) ? *(const float4*)(s + (size_t)(e0 + e) * D + q * 4)
                                  : make_float4(0.f, 0.f, 0.f, 0.f);
        unsigned* dst = sm + SA + e * 136 + (q >> 1) * 8 + (q & 1);
        dst[0] = f2tf(val.x); dst[2] = f2tf(val.y); dst[4] = f2tf(val.z); dst[6] = f2tf(val.w);
    }
    // ---- stage W1 -> sW (same layout) ----
    for (int i = tid; i < 128 * 32; i += NT) {
        int n = i >> 5, q = i & 31;
        float4 val = *(const float4*)(W1 + (size_t)n * D + q * 4);
        unsigned* dst = sm + SW + n * 136 + (q >> 1) * 8 + (q & 1);
        dst[0] = f2tf(val.x); dst[2] = f2tf(val.y); dst[4] = f2tf(val.z); dst[6] = f2tf(val.w);
    }
    // ---- stage Ww -> sWW [384][28] natural, cols >= NR zero ----
    for (int i = tid; i < 384 * 7; i += NT) {
        int n = i / 7, q = i - n * 7;
        unsigned* dst = sm + SWW + n * 28 + q * 4;
#pragma unroll
        for (int j = 0; j < 4; j++) {
            int cc = q * 4 + j;
            dst[j] = (cc < NR) ? f2tf(Ww[n * NR + cc]) : 0u;
        }
    }
    // ---- biases ----
    for (int i = tid; i < D; i += NT) smf[SB1 + i] = b1[i];
    for (int i = tid; i < 3 * D; i += NT) { smf[SB2 + i] = b2[i]; smf[SBW + i] = bw[i]; }
    // ---- per-edge: slot, meta(org+eid), fcut (natural layout) ----
    if (tid < ET) {
        int ge = e0 + tid;
        unsigned* fcrow = sm + SFC + tid * 28;
        if (ge < E) {
            sPos[tid] = g_pos[ge];
            float rx = r[ge * 3 + 0], ry = r[ge * 3 + 1], rz = r[ge * 3 + 2];
            float rn = sqrtf(rx * rx + ry * ry + rz * rz);
            float invg = rsqrtf(g_acc);   // reference: r / ||r||_F (whole array!)
            float4 meta;
            meta.x = rx * invg; meta.y = ry * invg; meta.z = rz * invg;
            meta.w = __int_as_float(ge);
            g_meta[sPos[tid]] = meta;
            float inv_rn = 1.f / rn;
            float theta = 0.62831853071795864f * rn;   // pi/RCUT * rn
            float sb = sinf(theta), cb = cosf(theta);
            float twocb = 2.f * cb;
            float sm1 = 0.f, scur = sb;
#pragma unroll
            for (int n = 0; n < NR; n++) {
                float rbf = scur * inv_rn;
                float fc = (rbf <= 5.0f) ? 0.5f * (__cosf(0.62831853071795864f * rbf) + 1.0f) : 0.0f;
                fcrow[n] = f2tf(fc);
                float nxt = twocb * scur - sm1;
                sm1 = scur; scur = nxt;
            }
            for (int n = NR; n < 28; n++) fcrow[n] = 0u;
        } else {
            sPos[tid] = 0;
            for (int n = 0; n < 28; n++) fcrow[n] = 0u;
        }
    }
    __syncthreads();

    // fragment base pointers (k-interleaved): LDS.64 yields (k=qc, k=qc+4)
    const unsigned* aBase0 = sm + SA + (m0 + qr) * 136 + qc * 2;        // mt rows: +16*136
    const unsigned* aBase1 = sm + SA + (m0 + 8 + qr) * 136 + qc * 2;
    const unsigned* bBase  = sm + SW + (n0 + qr) * 136 + qc * 2;        // nt rows: +8*136

    float acc[2][4][4];

#define GEMM_32x32() do {                                                          \
    _Pragma("unroll")                                                              \
    for (int mt = 0; mt < 2; mt++)                                                 \
        _Pragma("unroll")                                                          \
        for (int nt = 0; nt < 4; nt++)                                             \
            _Pragma("unroll")                                                      \
            for (int j = 0; j < 4; j++) acc[mt][nt][j] = 0.f;                      \
    _Pragma("unroll 4")                                                            \
    for (int kk = 0; kk < 16; kk++) {                                              \
        uint2 a00 = lds64(aBase0 + kk * 8);                                        \
        uint2 a01 = lds64(aBase1 + kk * 8);                                        \
        uint2 a10 = lds64(aBase0 + 16 * 136 + kk * 8);                             \
        uint2 a11 = lds64(aBase1 + 16 * 136 + kk * 8);                             \
        _Pragma("unroll")                                                          \
        for (int nt = 0; nt < 4; nt++) {                                           \
            uint2 b = lds64(bBase + nt * 8 * 136 + kk * 8);                        \
            mma_tf32(acc[0][nt], a00.x, a01.x, a00.y, a01.y, b.x, b.y);            \
            mma_tf32(acc[1][nt], a10.x, a11.x, a10.y, a11.y, b.x, b.y);            \
        }                                                                          \
    }                                                                              \
} while (0)

    // ================= GEMM1: h = silu(S @ W1^T + b1) =================
    GEMM_32x32();
    __syncthreads();   // all W1 + sA(s) reads complete

    // silu -> h overwrites sA rows (interleaved positions); stage W2 chunk 0
    {
        const int p0 = ((2 * qc) & 3) * 2 + (qc >> 1);   // pos of col 2qc in octet
#pragma unroll
        for (int mt = 0; mt < 2; mt++) {
            unsigned* hA = sm + SA + (m0 + mt * 16 + qr) * 136;
            unsigned* hB = hA + 8 * 136;
#pragma unroll
            for (int nt = 0; nt < 4; nt++) {
                int c0 = n0 + nt * 8 + 2 * qc;
                float bx = smf[SB1 + c0], by = smf[SB1 + c0 + 1];
                float x0 = acc[mt][nt][0] + bx, x1 = acc[mt][nt][1] + by;
                float x2 = acc[mt][nt][2] + bx, x3 = acc[mt][nt][3] + by;
                int base = (n0 + nt * 8) + p0;
                hA[base]     = f2tf(x0 / (1.f + __expf(-x0)));
                hA[base + 2] = f2tf(x1 / (1.f + __expf(-x1)));
                hB[base]     = f2tf(x2 / (1.f + __expf(-x2)));
                hB[base + 2] = f2tf(x3 / (1.f + __expf(-x3)));
            }
        }
    }
    for (int i = tid; i < 128 * 32; i += NT) {
        int n = i >> 5, q = i & 31;
        float4 val = *(const float4*)(W2 + (size_t)n * D + q * 4);
        unsigned* dst = sm + SW + n * 136 + (q >> 1) * 8 + (q & 1);
        dst[0] = f2tf(val.x); dst[2] = f2tf(val.y); dst[4] = f2tf(val.z); dst[6] = f2tf(val.w);
    }
    __syncthreads();

    // ================= chunks 0..2: phi -> gate -> store =================
#pragma unroll 1
    for (int c = 0; c < 3; c++) {
        GEMM_32x32();
        __syncthreads();   // sW reads done -> safe to restage

        if (c < 2) {       // stage next W2 chunk (overlaps gate/store below)
            const float* Wsrc = W2 + (size_t)(c + 1) * 128 * D;
            for (int i = tid; i < 128 * 32; i += NT) {
                int n = i >> 5, q = i & 31;
                float4 val = *(const float4*)(Wsrc + (size_t)n * D + q * 4);
                unsigned* dst = sm + SW + n * 136 + (q >> 1) * 8 + (q & 1);
                dst[0] = f2tf(val.x); dst[2] = f2tf(val.y); dst[4] = f2tf(val.z); dst[6] = f2tf(val.w);
            }
        }

        // gate (3 mma k-steps vs Ww) + bias + multiply + slot-ordered store
        float* gc = (c == 0) ? g_s0 : (c == 1) ? g_s1 : g_s2;
#pragma unroll
        for (int mt = 0; mt < 2; mt++) {
            int r0 = m0 + mt * 16 + qr, r1 = r0 + 8;
            bool l0 = (e0 + r0) < E, l1 = (e0 + r1) < E;
            int sl0 = sPos[r0], sl1 = sPos[r1];
            // fcut A fragments for this row pair
            unsigned fa[3][4];
#pragma unroll
            for (int t = 0; t < 3; t++) {
                const unsigned* pf = sm + SFC + r0 * 28 + t * 8 + qc;
                fa[t][0] = pf[0];
                fa[t][1] = pf[8 * 28];
                fa[t][2] = pf[4];
                fa[t][3] = pf[8 * 28 + 4];
            }
#pragma unroll
            for (int nt = 0; nt < 4; nt++) {
                float w4[4] = {0.f, 0.f, 0.f, 0.f};
                const unsigned* pWw = sm + SWW + (c * 128 + n0 + nt * 8 + qr) * 28 + qc;
#pragma unroll
                for (int t = 0; t < 3; t++)
                    mma_tf32(w4, fa[t][0], fa[t][1], fa[t][2], fa[t][3],
                             pWw[t * 8], pWw[t * 8 + 4]);
                int f0c = n0 + nt * 8 + 2 * qc;
                int ch  = c * 128 + f0c;
                float2 b2p = *(const float2*)(smf + SB2 + ch);
                float2 bwp = *(const float2*)(smf + SBW + ch);
                float o0 = (acc[mt][nt][0] + b2p.x) * (w4[0] + bwp.x);
                float o1 = (acc[mt][nt][1] + b2p.y) * (w4[1] + bwp.y);
                float o2 = (acc[mt][nt][2] + b2p.x) * (w4[2] + bwp.x);
                float o3 = (acc[mt][nt][3] + b2p.y) * (w4[3] + bwp.y);
                if (l0) *(float2*)(gc + (size_t)sl0 * D + f0c) = make_float2(o0, o1);
                if (l1) *(float2*)(gc + (size_t)sl1 * D + f0c) = make_float2(o2, o3);
            }
        }
        __syncthreads();   // restage complete before next chunk's mma
    }
#undef GEMM_32x32
}

// ============================================================ gather
// one CTA (128 threads) per node: sum contiguous slot range, write outputs.
__global__ void __launch_bounds__(128) gather_kernel(
    const float* __restrict__ v, float* __restrict__ out_v, float* __restrict__ out_s)
{
    int n = blockIdx.x;
    int beg = g_off[n], end = g_off[n + 1];
    int t = threadIdx.x;

    float av0 = 0.f, av1 = 0.f, av2 = 0.f, as1 = 0.f;
#pragma unroll 2
    for (int slot = beg; slot < end; slot++) {
        float4 meta = g_meta[slot];
        int eid = __float_as_int(meta.w);
        float s0 = g_s0[(size_t)slot * D + t];
        float s1 = g_s1[(size_t)slot * D + t];
        float s2 = g_s2[(size_t)slot * D + t];
        const float* vrow = v + (size_t)eid * 3 * D + t;
        av0 += s2 * meta.x + s0 * __ldg(vrow);
        av1 += s2 * meta.y + s0 * __ldg(vrow + D);
        av2 += s2 * meta.z + s0 * __ldg(vrow + 2 * D);
        as1 += s1;
    }
    float* ov = out_v + (size_t)n * 3 * D + t;
    ov[0]     = av0;
    ov[D]     = av1;
    ov[2 * D] = av2;
    out_s[(size_t)n * D + t] = as1;
}

// ============================================================
extern "C" void kernel_launch(void* const* d_in, const int* in_sizes, int n_in,
                              void* d_out, int out_size) {
    const float* s   = (const float*)d_in[0];
    const float* r   = (const float*)d_in[1];
    const float* v   = (const float*)d_in[2];
    const float* W1  = (const float*)d_in[3];
    const float* b1  = (const float*)d_in[4];
    const float* W2  = (const float*)d_in[5];
    const float* b2  = (const float*)d_in[6];
    const float* Ww  = (const float*)d_in[7];
    const float* bw  = (const float*)d_in[8];
    const int*   idx = (const int*)d_in[9];
    const int E = in_sizes[9];
    const int N = out_size / (4 * D);
    float* out_v = (float*)d_out;
    float* out_s = out_v + (size_t)N * 3 * D;

    cudaFuncSetAttribute(fused_kernel, cudaFuncAttributeMaxDynamicSharedMemorySize, (int)SMEM_BYTES);

    init_kernel<<<(N + 255) / 256, 256>>>(N);
    hist_norm_kernel<<<(E + 255) / 256, 256>>>(idx, r, E);
    scan_kernel<<<1, 1024>>>(N, E);
    pos_kernel<<<(E + 255) / 256, 256>>>(idx, E);

    int grid = (E + ET - 1) / ET;
    fused_kernel<<<grid, NT, SMEM_BYTES>>>(s, r, W1, W2, b1, b2, Ww, bw, E);

    gather_kernel<<<N, 128>>>(v, out_v, out_s);
}

// round 10
// speedup vs baseline: 2.2324x; 1.1272x over previous
#include <cuda_runtime.h>
#include <math.h>

constexpr int D    = 128;
constexpr int NR   = 20;
constexpr int ET   = 128;   // edges per CTA
constexpr int NT   = 512;   // threads per CTA (16 warps = 4M x 4N)
constexpr int EMAX = 200000;
constexpr int NBMAX = 16384;

// ---- device scratch (no allocations allowed) ----
__device__ float g_acc;
__device__ int   g_hist[NBMAX + 1];
__device__ int   g_off[NBMAX + 1];
__device__ int   g_cur[NBMAX + 1];
__device__ int   g_pos[EMAX];
__device__ float g_s0[(size_t)EMAX * D];
__device__ float g_s1[(size_t)EMAX * D];
__device__ float g_s2[(size_t)EMAX * D];
__device__ float4 g_meta[EMAX];            // per-slot: org.xyz, edge-id
// pre-converted weight images (exact smem layout, 16B-aligned for cp.async)
__device__ __align__(16) unsigned g_W1tf[128 * 136];
__device__ __align__(16) unsigned g_W2tf[3 * 128 * 136];
__device__ __align__(16) unsigned g_Wwtf[384 * 28];

// ---- smem layout (32-bit words) ----
// sA / sW use k-interleaved octets: word pos(k) = (k>>3)*8 + (k&3)*2 + ((k>>2)&1),
// row stride 136 (8 mod 32 -> conflict-free LDS.64 fragment loads).
constexpr int SA   = 0;                 // 128 x 136  tf32: s, then h (in place)
constexpr int SW   = SA  + 128 * 136;   // 128 x 136  tf32: W1, then W2 chunk c
constexpr int SWW  = SW  + 128 * 136;   // 384 x 28   tf32: Ww (cols>=NR zero)
constexpr int SFC  = SWW + 384 * 28;    // 128 x 28   tf32: fcut
constexpr int SB1  = SFC + 128 * 28;    // 128  f32
constexpr int SB2  = SB1 + 128;         // 384  f32
constexpr int SBW  = SB2 + 384;         // 384  f32
constexpr int SPOS = SBW + 384;         // 128  int
constexpr int SMEMN = SPOS + 128;       // 50176 words = 196 KB
constexpr size_t SMEM_BYTES = (size_t)SMEMN * 4;

// ---- tf32 / mma helpers ----
__device__ __forceinline__ unsigned f2tf(float x) {
    unsigned r; asm("cvt.rna.tf32.f32 %0, %1;" : "=r"(r) : "f"(x)); return r;
}
__device__ __forceinline__ void mma_tf32(float d[4],
    unsigned a0, unsigned a1, unsigned a2, unsigned a3, unsigned b0, unsigned b1) {
    asm("mma.sync.aligned.m16n8k8.row.col.f32.tf32.tf32.f32 "
        "{%0,%1,%2,%3}, {%4,%5,%6,%7}, {%8,%9}, {%0,%1,%2,%3};"
        : "+f"(d[0]), "+f"(d[1]), "+f"(d[2]), "+f"(d[3])
        : "r"(a0), "r"(a1), "r"(a2), "r"(a3), "r"(b0), "r"(b1));
}
__device__ __forceinline__ uint2 lds64(const unsigned* p) {
    uint2 v; asm("ld.shared.v2.b32 {%0,%1}, [%2];" : "=r"(v.x), "=r"(v.y)
                 : "l"((unsigned long long)__cvta_generic_to_shared(p)));
    return v;
}
__device__ __forceinline__ void cpa16(unsigned* smem_ptr, const unsigned* gptr) {
    unsigned saddr = (unsigned)__cvta_generic_to_shared(smem_ptr);
    asm volatile("cp.async.ca.shared.global [%0], [%1], 16;" :: "r"(saddr), "l"(gptr));
}
__device__ __forceinline__ void cpa_commit() { asm volatile("cp.async.commit_group;"); }
__device__ __forceinline__ void cpa_wait()   { asm volatile("cp.async.wait_group 0;"); }

// ============================================================ prologue
// convert all weights into smem-image layouts + zero histogram + g_acc
__global__ void wconv_kernel(const float* __restrict__ W1, const float* __restrict__ W2,
                             const float* __restrict__ Ww, int N) {
    int i = blockIdx.x * blockDim.x + threadIdx.x;
    if (i <= N) g_hist[i] = 0;
    if (i == 0) g_acc = 0.f;

    if (i < 4096) {                     // W1: 128 rows x 32 quads
        int n = i >> 5, q = i & 31;
        float4 val = *(const float4*)(W1 + (size_t)n * D + q * 4);
        unsigned* dst = g_W1tf + n * 136 + (q >> 1) * 8 + (q & 1);
        dst[0] = f2tf(val.x); dst[2] = f2tf(val.y); dst[4] = f2tf(val.z); dst[6] = f2tf(val.w);
    } else if (i < 4096 + 12288) {      // W2: 3 chunks x 128 rows x 32 quads
        int j = i - 4096;
        int c = j >> 12, rem = j & 4095;
        int n = rem >> 5, q = rem & 31;
        float4 val = *(const float4*)(W2 + (size_t)(c * 128 + n) * D + q * 4);
        unsigned* dst = g_W2tf + c * 128 * 136 + n * 136 + (q >> 1) * 8 + (q & 1);
        dst[0] = f2tf(val.x); dst[2] = f2tf(val.y); dst[4] = f2tf(val.z); dst[6] = f2tf(val.w);
    } else if (i < 4096 + 12288 + 2688) { // Ww: 384 rows x 7 quads (cols>=NR zero)
        int j = i - 16384;
        int n = j / 7, q = j - n * 7;
        unsigned* dst = g_Wwtf + n * 28 + q * 4;
#pragma unroll
        for (int jj = 0; jj < 4; jj++) {
            int cc = q * 4 + jj;
            dst[jj] = (cc < NR) ? f2tf(Ww[n * NR + cc]) : 0u;
        }
    }
}

// histogram + global ||r||^2 in one pass
__global__ void hist_norm_kernel(const int* __restrict__ idx_i, const float* __restrict__ r, int E) {
    __shared__ float red[256];
    int e = blockIdx.x * blockDim.x + threadIdx.x;
    float s = 0.f;
    if (e < E) {
        atomicAdd(&g_hist[idx_i[e]], 1);
        float rx = r[e * 3 + 0], ry = r[e * 3 + 1], rz = r[e * 3 + 2];
        s = rx * rx + ry * ry + rz * rz;
    }
    red[threadIdx.x] = s;
    __syncthreads();
    for (int off = 128; off > 0; off >>= 1) {
        if (threadIdx.x < off) red[threadIdx.x] += red[threadIdx.x + off];
        __syncthreads();
    }
    if (threadIdx.x == 0) atomicAdd(&g_acc, red[0]);
}

__global__ void scan_kernel(int N, int E) {
    __shared__ int sh[1024];
    int t = threadIdx.x;
    int CH = (N + 1023) >> 10;
    int b = t * CH, e = min(b + CH, N);
    int s = 0;
    for (int i = b; i < e; i++) s += g_hist[i];
    sh[t] = s;
    __syncthreads();
    for (int off = 1; off < 1024; off <<= 1) {
        int add = (t >= off) ? sh[t - off] : 0;
        __syncthreads();
        sh[t] += add;
        __syncthreads();
    }
    int excl = sh[t] - s;
    for (int i = b; i < e; i++) {
        g_off[i] = excl;
        g_cur[i] = excl;
        excl += g_hist[i];
    }
    if (t == 0) g_off[N] = E;
}

__global__ void pos_kernel(const int* __restrict__ idx_i, int E) {
    int e = blockIdx.x * blockDim.x + threadIdx.x;
    if (e < E) g_pos[e] = atomicAdd(&g_cur[idx_i[e]], 1);
}

// ============================================================ fused
__global__ void __launch_bounds__(NT, 1) fused_kernel(
    const float* __restrict__ s, const float* __restrict__ r,
    const float* __restrict__ b1, const float* __restrict__ b2,
    const float* __restrict__ bw, int E)
{
    extern __shared__ unsigned sm[];
    float* smf = reinterpret_cast<float*>(sm);
    int*   sPos = reinterpret_cast<int*>(sm + SPOS);

    const int tid  = threadIdx.x;
    const int lane = tid & 31;
    const int wrp  = tid >> 5;
    const int e0   = blockIdx.x * ET;
    const int mw   = wrp >> 2;
    const int nw   = wrp & 3;
    const int m0   = mw * 32;
    const int n0   = nw * 32;
    const int qr   = lane >> 2;
    const int qc   = lane & 3;

    // ---- async stage W1 + Ww (pre-converted images, 16B chunks) ----
    for (int i = tid; i < 4352; i += NT) cpa16(sm + SW + i * 4, g_W1tf + i * 4);
    for (int i = tid; i < 2688; i += NT) cpa16(sm + SWW + i * 4, g_Wwtf + i * 4);
    cpa_commit();

    // ---- stage s -> sA (tf32, k-interleaved, stride 136) ----
    for (int i = tid; i < 128 * 32; i += NT) {
        int e = i >> 5, q = i & 31;
        float4 val = (e0 + e < E) ? *(const float4*)(s + (size_t)(e0 + e) * D + q * 4)
                                  : make_float4(0.f, 0.f, 0.f, 0.f);
        unsigned* dst = sm + SA + e * 136 + (q >> 1) * 8 + (q & 1);
        dst[0] = f2tf(val.x); dst[2] = f2tf(val.y); dst[4] = f2tf(val.z); dst[6] = f2tf(val.w);
    }
    // ---- biases ----
    for (int i = tid; i < D; i += NT) smf[SB1 + i] = b1[i];
    for (int i = tid; i < 3 * D; i += NT) { smf[SB2 + i] = b2[i]; smf[SBW + i] = bw[i]; }
    // ---- per-edge: slot, meta(org+eid), fcut ----
    if (tid < ET) {
        int ge = e0 + tid;
        unsigned* fcrow = sm + SFC + tid * 28;
        if (ge < E) {
            sPos[tid] = g_pos[ge];
            float rx = r[ge * 3 + 0], ry = r[ge * 3 + 1], rz = r[ge * 3 + 2];
            float rn = sqrtf(rx * rx + ry * ry + rz * rz);
            float invg = rsqrtf(g_acc);   // reference: r / ||r||_F (whole array!)
            float4 meta;
            meta.x = rx * invg; meta.y = ry * invg; meta.z = rz * invg;
            meta.w = __int_as_float(ge);
            g_meta[sPos[tid]] = meta;
            float inv_rn = 1.f / rn;
            float theta = 0.62831853071795864f * rn;   // pi/RCUT * rn
            float sb = sinf(theta), cb = cosf(theta);
            float twocb = 2.f * cb;
            float sm1 = 0.f, scur = sb;
#pragma unroll
            for (int n = 0; n < NR; n++) {
                float rbf = scur * inv_rn;
                float fc = (rbf <= 5.0f) ? 0.5f * (__cosf(0.62831853071795864f * rbf) + 1.0f) : 0.0f;
                fcrow[n] = f2tf(fc);
                float nxt = twocb * scur - sm1;
                sm1 = scur; scur = nxt;
            }
            for (int n = NR; n < 28; n++) fcrow[n] = 0u;
        } else {
            sPos[tid] = 0;
            for (int n = 0; n < 28; n++) fcrow[n] = 0u;
        }
    }
    cpa_wait();
    __syncthreads();

    // fragment base pointers (k-interleaved): LDS.64 yields (k=qc, k=qc+4)
    const unsigned* aBase0 = sm + SA + (m0 + qr) * 136 + qc * 2;
    const unsigned* aBase1 = sm + SA + (m0 + 8 + qr) * 136 + qc * 2;
    const unsigned* bBase  = sm + SW + (n0 + qr) * 136 + qc * 2;

    float acc[2][4][4];

#define GEMM_32x32() do {                                                          \
    _Pragma("unroll")                                                              \
    for (int mt = 0; mt < 2; mt++)                                                 \
        _Pragma("unroll")                                                          \
        for (int nt = 0; nt < 4; nt++)                                             \
            _Pragma("unroll")                                                      \
            for (int j = 0; j < 4; j++) acc[mt][nt][j] = 0.f;                      \
    _Pragma("unroll 4")                                                            \
    for (int kk = 0; kk < 16; kk++) {                                              \
        uint2 a00 = lds64(aBase0 + kk * 8);                                        \
        uint2 a01 = lds64(aBase1 + kk * 8);                                        \
        uint2 a10 = lds64(aBase0 + 16 * 136 + kk * 8);                             \
        uint2 a11 = lds64(aBase1 + 16 * 136 + kk * 8);                             \
        _Pragma("unroll")                                                          \
        for (int nt = 0; nt < 4; nt++) {                                           \
            uint2 b = lds64(bBase + nt * 8 * 136 + kk * 8);                        \
            mma_tf32(acc[0][nt], a00.x, a01.x, a00.y, a01.y, b.x, b.y);            \
            mma_tf32(acc[1][nt], a10.x, a11.x, a10.y, a11.y, b.x, b.y);            \
        }                                                                          \
    }                                                                              \
} while (0)

    // ================= GEMM1: h = silu(S @ W1^T + b1) =================
    GEMM_32x32();
    __syncthreads();   // all W1 + sA(s) reads complete

    // prefetch W2 chunk 0 (async), then silu -> h overwrites sA rows
    for (int i = tid; i < 4352; i += NT) cpa16(sm + SW + i * 4, g_W2tf + i * 4);
    cpa_commit();
    {
        const int p0 = ((2 * qc) & 3) * 2 + (qc >> 1);   // pos of col 2qc in octet
#pragma unroll
        for (int mt = 0; mt < 2; mt++) {
            unsigned* hA = sm + SA + (m0 + mt * 16 + qr) * 136;
            unsigned* hB = hA + 8 * 136;
#pragma unroll
            for (int nt = 0; nt < 4; nt++) {
                int c0 = n0 + nt * 8 + 2 * qc;
                float bx = smf[SB1 + c0], by = smf[SB1 + c0 + 1];
                float x0 = acc[mt][nt][0] + bx, x1 = acc[mt][nt][1] + by;
                float x2 = acc[mt][nt][2] + bx, x3 = acc[mt][nt][3] + by;
                int base = (n0 + nt * 8) + p0;
                hA[base]     = f2tf(x0 / (1.f + __expf(-x0)));
                hA[base + 2] = f2tf(x1 / (1.f + __expf(-x1)));
                hB[base]     = f2tf(x2 / (1.f + __expf(-x2)));
                hB[base + 2] = f2tf(x3 / (1.f + __expf(-x3)));
            }
        }
    }
    cpa_wait();
    __syncthreads();

    // ================= chunks 0..2: phi -> gate -> store =================
#pragma unroll 1
    for (int c = 0; c < 3; c++) {
        GEMM_32x32();
        __syncthreads();   // sW reads done -> safe to restage

        if (c < 2) {       // async prefetch next W2 chunk; hides behind gate/store
            const unsigned* src = g_W2tf + (c + 1) * 128 * 136;
            for (int i = tid; i < 4352; i += NT) cpa16(sm + SW + i * 4, src + i * 4);
            cpa_commit();
        }

        // gate (3 mma k-steps vs Ww) + bias + multiply + slot-ordered store
        float* gc = (c == 0) ? g_s0 : (c == 1) ? g_s1 : g_s2;
#pragma unroll
        for (int mt = 0; mt < 2; mt++) {
            int r0 = m0 + mt * 16 + qr, r1 = r0 + 8;
            bool l0 = (e0 + r0) < E, l1 = (e0 + r1) < E;
            int sl0 = sPos[r0], sl1 = sPos[r1];
            unsigned fa[3][4];
#pragma unroll
            for (int t = 0; t < 3; t++) {
                const unsigned* pf = sm + SFC + r0 * 28 + t * 8 + qc;
                fa[t][0] = pf[0];
                fa[t][1] = pf[8 * 28];
                fa[t][2] = pf[4];
                fa[t][3] = pf[8 * 28 + 4];
            }
#pragma unroll
            for (int nt = 0; nt < 4; nt++) {
                float w4[4] = {0.f, 0.f, 0.f, 0.f};
                const unsigned* pWw = sm + SWW + (c * 128 + n0 + nt * 8 + qr) * 28 + qc;
#pragma unroll
                for (int t = 0; t < 3; t++)
                    mma_tf32(w4, fa[t][0], fa[t][1], fa[t][2], fa[t][3],
                             pWw[t * 8], pWw[t * 8 + 4]);
                int f0c = n0 + nt * 8 + 2 * qc;
                int ch  = c * 128 + f0c;
                float2 b2p = *(const float2*)(smf + SB2 + ch);
                float2 bwp = *(const float2*)(smf + SBW + ch);
                float o0 = (acc[mt][nt][0] + b2p.x) * (w4[0] + bwp.x);
                float o1 = (acc[mt][nt][1] + b2p.y) * (w4[1] + bwp.y);
                float o2 = (acc[mt][nt][2] + b2p.x) * (w4[2] + bwp.x);
                float o3 = (acc[mt][nt][3] + b2p.y) * (w4[3] + bwp.y);
                if (l0) *(float2*)(gc + (size_t)sl0 * D + f0c) = make_float2(o0, o1);
                if (l1) *(float2*)(gc + (size_t)sl1 * D + f0c) = make_float2(o2, o3);
            }
        }
        cpa_wait();
        __syncthreads();   // restage complete before next chunk's mma
    }
#undef GEMM_32x32
}

// ============================================================ gather
__global__ void __launch_bounds__(128) gather_kernel(
    const float* __restrict__ v, float* __restrict__ out_v, float* __restrict__ out_s)
{
    int n = blockIdx.x;
    int beg = g_off[n], end = g_off[n + 1];
    int t = threadIdx.x;

    float av0 = 0.f, av1 = 0.f, av2 = 0.f, as1 = 0.f;
#pragma unroll 2
    for (int slot = beg; slot < end; slot++) {
        float4 meta = g_meta[slot];
        int eid = __float_as_int(meta.w);
        float s0 = g_s0[(size_t)slot * D + t];
        float s1 = g_s1[(size_t)slot * D + t];
        float s2 = g_s2[(size_t)slot * D + t];
        const float* vrow = v + (size_t)eid * 3 * D + t;
        av0 += s2 * meta.x + s0 * __ldg(vrow);
        av1 += s2 * meta.y + s0 * __ldg(vrow + D);
        av2 += s2 * meta.z + s0 * __ldg(vrow + 2 * D);
        as1 += s1;
    }
    float* ov = out_v + (size_t)n * 3 * D + t;
    ov[0]     = av0;
    ov[D]     = av1;
    ov[2 * D] = av2;
    out_s[(size_t)n * D + t] = as1;
}

// ============================================================
extern "C" void kernel_launch(void* const* d_in, const int* in_sizes, int n_in,
                              void* d_out, int out_size) {
    const float* s   = (const float*)d_in[0];
    const float* r   = (const float*)d_in[1];
    const float* v   = (const float*)d_in[2];
    const float* W1  = (const float*)d_in[3];
    const float* b1  = (const float*)d_in[4];
    const float* W2  = (const float*)d_in[5];
    const float* b2  = (const float*)d_in[6];
    const float* Ww  = (const float*)d_in[7];
    const float* bw  = (const float*)d_in[8];
    const int*   idx = (const int*)d_in[9];
    const int E = in_sizes[9];
    const int N = out_size / (4 * D);
    float* out_v = (float*)d_out;
    float* out_s = out_v + (size_t)N * 3 * D;

    cudaFuncSetAttribute(fused_kernel, cudaFuncAttributeMaxDynamicSharedMemorySize, (int)SMEM_BYTES);

    wconv_kernel<<<80, 256>>>(W1, W2, Ww, N);   // weights + init (covers 19072 & N+1)
    hist_norm_kernel<<<(E + 255) / 256, 256>>>(idx, r, E);
    scan_kernel<<<1, 1024>>>(N, E);
    pos_kernel<<<(E + 255) / 256, 256>>>(idx, E);

    int grid = (E + ET - 1) / ET;
    fused_kernel<<<grid, NT, SMEM_BYTES>>>(s, r, b1, b2, bw, E);

    gather_kernel<<<N, 128>>>(v, out_v, out_s);
}